// round 5
// baseline (speedup 1.0000x reference)
#include <cuda_runtime.h>
#include <cuda_bf16.h>

#define BATCH  64
#define NPTS   1024
#define CHUNKS 32
#define JCH    (NPTS / CHUNKS)      // 32 j per block
#define NJP    (JCH / 2)            // 16 j-pairs
#define TPB    256
#define SPT    4                    // consecutive shifts per thread

// Deterministic scratch (no atomics, no allocations).
__device__ float g_partial[CHUNKS][BATCH][NPTS];  // 8 MB
__device__ float g_min[BATCH];

typedef unsigned long long u64;

// ---- packed f32x2 helpers ---------------------------------------------------
__device__ __forceinline__ void upk2(u64 v, float& a, float& b) {
    asm("mov.b64 {%0, %1}, %2;" : "=f"(a), "=f"(b) : "l"(v));
}
__device__ __forceinline__ u64 pk2(float a, float b) {
    u64 r; asm("mov.b64 %0, {%1, %2};" : "=l"(r) : "f"(a), "f"(b)); return r;
}
__device__ __forceinline__ u64 addx2(u64 a, u64 b) {
    u64 r; asm("add.rn.f32x2 %0, %1, %2;" : "=l"(r) : "l"(a), "l"(b)); return r;
}
__device__ __forceinline__ u64 mulx2(u64 a, u64 b) {
    u64 r; asm("mul.rn.f32x2 %0, %1, %2;" : "=l"(r) : "l"(a), "l"(b)); return r;
}
__device__ __forceinline__ u64 fmx2(u64 a, u64 b, u64 c) {
    u64 r; asm("fma.rn.f32x2 %0, %1, %2, %3;" : "=l"(r) : "l"(a), "l"(b), "l"(c)); return r;
}
__device__ __forceinline__ float sqrtapx(float x) {
    float r; asm("sqrt.approx.f32 %0, %1;" : "=f"(r) : "f"(x)); return r;
}

// ---------------------------------------------------------------------------
// Kernel 1: partial shift sums.
// Grid (CHUNKS, BATCH), TPB=256. Thread t owns shifts 4t..4t+3, walks the
// chunk's j values in pairs. Negated target stored in smem TWICE per
// coordinate: natural alignment (TXe) and shifted-by-one (TXo[i] = TX[i+1]),
// so all four shift alignments of a (j,j+1) pair are direct aligned LDS.64s:
//   m=0 -> TXeU[e/2]   (new)        m=2 -> TXeU[e/2-1] (prev iter's load)
//   m=1 -> TXoU[e/2-1] (new)        m=3 -> TXoU[e/2-2] (prev iter's load)
// Zero pack MOVs in the hot loop.
// ---------------------------------------------------------------------------
__global__ void __launch_bounds__(TPB, 6)
snake_main_kernel(const float2* __restrict__ x, const float2* __restrict__ tg)
{
    __shared__ __align__(16) float TXe[2 * NPTS];  // -t.x[i mod N]
    __shared__ __align__(16) float TXo[2 * NPTS];  // -t.x[(i+1) mod N]
    __shared__ __align__(16) float TYe[2 * NPTS];
    __shared__ __align__(16) float TYo[2 * NPTS];
    __shared__ u64 XPX[NJP];                       // (x_j.x, x_{j+1}.x)
    __shared__ u64 XPY[NJP];

    const int b     = blockIdx.y;
    const int chunk = blockIdx.x;
    const int j0    = chunk * JCH;
    const int t     = threadIdx.x;

    const float2* __restrict__ tb = tg + b * NPTS;
    const float2* __restrict__ xb = x  + b * NPTS;

    #pragma unroll
    for (int i = t; i < 2 * NPTS; i += TPB) {
        float2 tv = tb[i & (NPTS - 1)];
        float nx = -tv.x, ny = -tv.y;
        TXe[i] = nx;  TYe[i] = ny;
        int o = (i + 2 * NPTS - 1) & (2 * NPTS - 1);   // TXo[i-1] = TX[i]
        TXo[o] = nx;  TYo[o] = ny;
    }
    if (t < NJP) {
        float4 q = *(const float4*)(xb + j0 + 2 * t);   // (xj.x,xj.y,xj1.x,xj1.y)
        XPX[t] = pk2(q.x, q.z);
        XPY[t] = pk2(q.y, q.w);
    }
    __syncthreads();

    const u64* __restrict__ TXeU = (const u64*)TXe;
    const u64* __restrict__ TXoU = (const u64*)TXo;
    const u64* __restrict__ TYeU = (const u64*)TYe;
    const u64* __restrict__ TYoU = (const u64*)TYo;

    const int s0 = SPT * t;                 // first shift owned by this thread
    const int p0 = (j0 - s0 + NPTS) >> 1;   // pair index for jj=0, >= 2

    float a00=0,a01=0,a10=0,a11=0,a20=0,a21=0,a30=0,a31=0;

    // Preload window (prev-iteration equivalents).
    u64 ax  = TXeU[p0 - 1];   // pair (e-2, e-1)
    u64 ay  = TYeU[p0 - 1];
    u64 aox = TXoU[p0 - 2];   // pair (e-3, e-2)
    u64 aoy = TYoU[p0 - 2];

    #pragma unroll
    for (int jj = 0; jj < NJP; ++jj) {
        const int p  = p0 + jj;
        u64 bx  = TXeU[p];         // (e, e+1)
        u64 by  = TYeU[p];
        u64 box = TXoU[p - 1];     // (e-1, e)
        u64 boy = TYoU[p - 1];
        u64 xpx = XPX[jj];         // broadcast
        u64 xpy = XPY[jj];

        {   // m = 0
            u64 dx = addx2(xpx, bx), dy = addx2(xpy, by);
            u64 d2 = fmx2(dy, dy, mulx2(dx, dx));
            float lo, hi; upk2(d2, lo, hi);
            a00 += sqrtapx(lo); a01 += sqrtapx(hi);
        }
        {   // m = 1
            u64 dx = addx2(xpx, box), dy = addx2(xpy, boy);
            u64 d2 = fmx2(dy, dy, mulx2(dx, dx));
            float lo, hi; upk2(d2, lo, hi);
            a10 += sqrtapx(lo); a11 += sqrtapx(hi);
        }
        {   // m = 2
            u64 dx = addx2(xpx, ax), dy = addx2(xpy, ay);
            u64 d2 = fmx2(dy, dy, mulx2(dx, dx));
            float lo, hi; upk2(d2, lo, hi);
            a20 += sqrtapx(lo); a21 += sqrtapx(hi);
        }
        {   // m = 3
            u64 dx = addx2(xpx, aox), dy = addx2(xpy, aoy);
            u64 d2 = fmx2(dy, dy, mulx2(dx, dx));
            float lo, hi; upk2(d2, lo, hi);
            a30 += sqrtapx(lo); a31 += sqrtapx(hi);
        }

        // rotate window (renamed under full unroll)
        ax = bx;  ay = by;  aox = box;  aoy = boy;
    }

    g_partial[chunk][b][s0 + 0] = a00 + a01;
    g_partial[chunk][b][s0 + 1] = a10 + a11;
    g_partial[chunk][b][s0 + 2] = a20 + a21;
    g_partial[chunk][b][s0 + 3] = a30 + a31;
}

// ---------------------------------------------------------------------------
// Kernel 2: per-batch reduce. Grid: (BATCH), 1024 threads.
// Sum partials over chunks (fixed order), then block-min over the 1024 shifts.
// ---------------------------------------------------------------------------
__global__ void __launch_bounds__(1024)
snake_reduce_kernel(void)
{
    const int b = blockIdx.x;
    const int s = threadIdx.x;

    float sum = 0.0f;
    #pragma unroll
    for (int c = 0; c < CHUNKS; ++c)
        sum += g_partial[c][b][s];

    float v = sum;
    #pragma unroll
    for (int o = 16; o > 0; o >>= 1)
        v = fminf(v, __shfl_xor_sync(0xFFFFFFFFu, v, o));

    __shared__ float warpmin[32];
    if ((threadIdx.x & 31) == 0) warpmin[threadIdx.x >> 5] = v;
    __syncthreads();

    if (threadIdx.x < 32) {
        v = warpmin[threadIdx.x];
        #pragma unroll
        for (int o = 16; o > 0; o >>= 1)
            v = fminf(v, __shfl_xor_sync(0xFFFFFFFFu, v, o));
        if (threadIdx.x == 0) g_min[b] = v;   // min of raw sums; /N folded below
    }
}

// ---------------------------------------------------------------------------
// Kernel 3: final mean over batch. 1 block, 32 threads.
// ---------------------------------------------------------------------------
__global__ void snake_final_kernel(float* __restrict__ out)
{
    float v = g_min[threadIdx.x] + g_min[threadIdx.x + 32];
    #pragma unroll
    for (int o = 16; o > 0; o >>= 1)
        v += __shfl_xor_sync(0xFFFFFFFFu, v, o);
    if (threadIdx.x == 0)
        out[0] = v * (1.0f / (float)(BATCH * NPTS));
}

// ---------------------------------------------------------------------------
extern "C" void kernel_launch(void* const* d_in, const int* in_sizes, int n_in,
                              void* d_out, int out_size)
{
    const float2* x  = (const float2*)d_in[0];
    const float2* tg = (const float2*)d_in[1];
    float* out = (float*)d_out;

    dim3 grid(CHUNKS, BATCH);
    snake_main_kernel<<<grid, TPB>>>(x, tg);
    snake_reduce_kernel<<<BATCH, 1024>>>();
    snake_final_kernel<<<1, 32>>>(out);
}

// round 6
// speedup vs baseline: 1.4815x; 1.4815x over previous
#include <cuda_runtime.h>
#include <cuda_bf16.h>

#define BATCH  64
#define NPTS   1024
#define CHUNKS 16
#define JCH    (NPTS / CHUNKS)      // 64 j per block
#define NJP    (JCH / 2)            // 32 j-pairs
#define TPB    256
#define PADN   1280                 // 1024 u64 + swizzle padding
#define PADF   (2 * PADN)           // floats per smem array

// Deterministic scratch (no atomics, no allocations).
__device__ float g_partial[CHUNKS][BATCH][NPTS];  // 4 MB
__device__ float g_min4[BATCH * 4];

typedef unsigned long long u64;

// ---- packed f32x2 helpers ---------------------------------------------------
__device__ __forceinline__ void upk2(u64 v, float& a, float& b) {
    asm("mov.b64 {%0, %1}, %2;" : "=f"(a), "=f"(b) : "l"(v));
}
__device__ __forceinline__ u64 pk2(float a, float b) {
    u64 r; asm("mov.b64 %0, {%1, %2};" : "=l"(r) : "f"(a), "f"(b)); return r;
}
__device__ __forceinline__ u64 addx2(u64 a, u64 b) {
    u64 r; asm("add.rn.f32x2 %0, %1, %2;" : "=l"(r) : "l"(a), "l"(b)); return r;
}
__device__ __forceinline__ u64 mulx2(u64 a, u64 b) {
    u64 r; asm("mul.rn.f32x2 %0, %1, %2;" : "=l"(r) : "l"(a), "l"(b)); return r;
}
__device__ __forceinline__ u64 fmx2(u64 a, u64 b, u64 c) {
    u64 r; asm("fma.rn.f32x2 %0, %1, %2, %3;" : "=l"(r) : "l"(a), "l"(b), "l"(c)); return r;
}
__device__ __forceinline__ float sqrtapx(float x) {
    float r; asm("sqrt.approx.f32 %0, %1;" : "=f"(r) : "f"(x)); return r;
}

// Bank-conflict swizzle on u64 index: phi(m) = m + (m >> 2).
// For the hot-loop lane pattern m = C - 2t this covers every bank-pair
// exactly twice -> LDS.64 at the 2-wavefront optimum.
__device__ __forceinline__ int swzm(int m) { return m + (m >> 2); }
// Same swizzle expressed on a float index i (m = i>>1).
__device__ __forceinline__ int swzf(int i) {
    return 2 * ((i >> 1) + (i >> 3)) + (i & 1);
}

// ---------------------------------------------------------------------------
// Kernel 1: partial shift sums.
// Grid (CHUNKS, BATCH), TPB=256. Thread t owns shifts 4t..4t+3, walks the
// chunk's j in pairs. Negated target in 4 swizzled SoA arrays per coord
// alignment (even / odd-shifted), so every shift alignment of a (j,j+1)
// pair is a direct LDS.64; m=2,3 reuse m=0,1's previous-iteration loads.
// Zero pack MOVs, 4 new LDS.64 per 8 distances.
// ---------------------------------------------------------------------------
__global__ void __launch_bounds__(TPB, 4)
snake_main_kernel(const float2* __restrict__ x, const float2* __restrict__ tg)
{
    __shared__ __align__(16) float SH[4][PADF];   // TXe, TXo, TYe, TYo (swizzled)
    __shared__ u64 XPX[NJP];                      // (x_j.x, x_{j+1}.x)
    __shared__ u64 XPY[NJP];

    const int b     = blockIdx.y;
    const int chunk = blockIdx.x;
    const int j0    = chunk * JCH;
    const int t     = threadIdx.x;

    const float2* __restrict__ tb = tg + b * NPTS;
    const float2* __restrict__ xb = x  + b * NPTS;

    float* __restrict__ TXe = SH[0];
    float* __restrict__ TXo = SH[1];
    float* __restrict__ TYe = SH[2];
    float* __restrict__ TYo = SH[3];

    #pragma unroll
    for (int i = t; i < 2 * NPTS; i += TPB) {
        float2 tv = tb[i & (NPTS - 1)];
        float nx = -tv.x, ny = -tv.y;
        int pe = swzf(i);
        TXe[pe] = nx;  TYe[pe] = ny;
        int j  = (i + 2 * NPTS - 1) & (2 * NPTS - 1);  // TXo[i-1] = TX[i]
        int po = swzf(j);
        TXo[po] = nx;  TYo[po] = ny;
    }
    if (t < NJP) {
        float4 q = *(const float4*)(xb + j0 + 2 * t);   // (xj.x,xj.y,xj1.x,xj1.y)
        XPX[t] = pk2(q.x, q.z);
        XPY[t] = pk2(q.y, q.w);
    }
    __syncthreads();

    const u64* __restrict__ TXeU = (const u64*)SH[0];
    const u64* __restrict__ TXoU = (const u64*)SH[1];
    const u64* __restrict__ TYeU = (const u64*)SH[2];
    const u64* __restrict__ TYoU = (const u64*)SH[3];

    const int s0 = 4 * t;                      // first shift owned by thread
    const int p0 = ((j0 + NPTS) >> 1) - 2 * t; // u64 pair index at q=0 (>= 2)

    float a0=0, a1=0, a2=0, a3=0, a0h=0, a1h=0, a2h=0, a3h=0;

    // Preload previous-iteration window.
    u64 axe = TXeU[swzm(p0 - 1)];
    u64 aye = TYeU[swzm(p0 - 1)];
    u64 axo = TXoU[swzm(p0 - 2)];
    u64 ayo = TYoU[swzm(p0 - 2)];

    #pragma unroll 8
    for (int q = 0; q < NJP; ++q) {
        const int m  = p0 + q;
        const int fe = swzm(m);
        const int fo = swzm(m - 1);
        u64 bxe = TXeU[fe];        // (T[f], T[f+1]).x  for shift s0
        u64 bye = TYeU[fe];
        u64 bxo = TXoU[fo];        // (T[f-1], T[f]).x  for shift s0+1
        u64 byo = TYoU[fo];
        u64 xpx = XPX[q];          // broadcast
        u64 xpy = XPY[q];

        {   // m = 0 (shift s0)
            u64 dx = addx2(xpx, bxe), dy = addx2(xpy, bye);
            u64 d2 = fmx2(dy, dy, mulx2(dx, dx));
            float lo, hi; upk2(d2, lo, hi);
            a0 += sqrtapx(lo); a0h += sqrtapx(hi);
        }
        {   // m = 1 (shift s0+1)
            u64 dx = addx2(xpx, bxo), dy = addx2(xpy, byo);
            u64 d2 = fmx2(dy, dy, mulx2(dx, dx));
            float lo, hi; upk2(d2, lo, hi);
            a1 += sqrtapx(lo); a1h += sqrtapx(hi);
        }
        {   // m = 2 (shift s0+2): previous iteration's even load
            u64 dx = addx2(xpx, axe), dy = addx2(xpy, aye);
            u64 d2 = fmx2(dy, dy, mulx2(dx, dx));
            float lo, hi; upk2(d2, lo, hi);
            a2 += sqrtapx(lo); a2h += sqrtapx(hi);
        }
        {   // m = 3 (shift s0+3): previous iteration's odd load
            u64 dx = addx2(xpx, axo), dy = addx2(xpy, ayo);
            u64 d2 = fmx2(dy, dy, mulx2(dx, dx));
            float lo, hi; upk2(d2, lo, hi);
            a3 += sqrtapx(lo); a3h += sqrtapx(hi);
        }

        axe = bxe; aye = bye; axo = bxo; ayo = byo;
    }

    float4 outv = make_float4(a0 + a0h, a1 + a1h, a2 + a2h, a3 + a3h);
    *(float4*)&g_partial[chunk][b][s0] = outv;   // 16B aligned (s0 = 4t)
}

// ---------------------------------------------------------------------------
// Kernel 2: stage-1 reduce. Grid (4, BATCH), 256 threads.
// Thread handles shift s = q*256 + t: sum over chunks, block-min -> g_min4.
// ---------------------------------------------------------------------------
__global__ void __launch_bounds__(256)
snake_reduce_kernel(void)
{
    const int b = blockIdx.y;
    const int s = blockIdx.x * 256 + threadIdx.x;

    float sum = 0.0f;
    #pragma unroll
    for (int c = 0; c < CHUNKS; ++c)
        sum += g_partial[c][b][s];

    float v = sum;
    #pragma unroll
    for (int o = 16; o > 0; o >>= 1)
        v = fminf(v, __shfl_xor_sync(0xFFFFFFFFu, v, o));

    __shared__ float warpmin[8];
    if ((threadIdx.x & 31) == 0) warpmin[threadIdx.x >> 5] = v;
    __syncthreads();

    if (threadIdx.x < 8) {
        v = warpmin[threadIdx.x];
        v = fminf(v, __shfl_xor_sync(0xFFu, v, 4));
        v = fminf(v, __shfl_xor_sync(0xFFu, v, 2));
        v = fminf(v, __shfl_xor_sync(0xFFu, v, 1));
        if (threadIdx.x == 0) g_min4[b * 4 + blockIdx.x] = v;
    }
}

// ---------------------------------------------------------------------------
// Kernel 3: final. 1 block, 256 threads: min over the 4 quarters per batch,
// then fixed-order sum over batches, scaled by 1/(B*N).
// ---------------------------------------------------------------------------
__global__ void __launch_bounds__(256)
snake_final_kernel(float* __restrict__ out)
{
    __shared__ float sh[64];
    int t = threadIdx.x;

    float v = g_min4[t];                       // t = b*4 + q
    v = fminf(v, __shfl_xor_sync(0xFFFFFFFFu, v, 1));
    v = fminf(v, __shfl_xor_sync(0xFFFFFFFFu, v, 2));  // lanes q=0 hold min_b
    if ((t & 3) == 0) sh[t >> 2] = v;
    __syncthreads();

    if (t < 64) {
        float s = sh[t];
        #pragma unroll
        for (int o = 16; o > 0; o >>= 1)
            s += __shfl_xor_sync(0xFFFFFFFFu, s, o);
        if (t == 0)  sh[0] = s;   // sum of b = 0..31
        if (t == 32) sh[1] = s;   // sum of b = 32..63
    }
    __syncthreads();
    if (t == 0)
        out[0] = (sh[0] + sh[1]) * (1.0f / (float)(BATCH * NPTS));
}

// ---------------------------------------------------------------------------
extern "C" void kernel_launch(void* const* d_in, const int* in_sizes, int n_in,
                              void* d_out, int out_size)
{
    const float2* x  = (const float2*)d_in[0];
    const float2* tg = (const float2*)d_in[1];
    float* out = (float*)d_out;

    dim3 grid(CHUNKS, BATCH);
    snake_main_kernel<<<grid, TPB>>>(x, tg);
    dim3 rgrid(4, BATCH);
    snake_reduce_kernel<<<rgrid, 256>>>();
    snake_final_kernel<<<1, 256>>>(out);
}

// round 7
// speedup vs baseline: 1.4929x; 1.0077x over previous
#include <cuda_runtime.h>
#include <cuda_bf16.h>

#define BATCH  64
#define NPTS   1024
#define CHUNKS 16
#define JCH    (NPTS / CHUNKS)      // 64 j per block
#define NJP    (JCH / 2)            // 32 j-pairs
#define TPB    256
#define PADN   1032                 // 1024 u64 + swizzle headroom (max phi = 1026)

// Deterministic scratch (no device-side allocation; zero-initialized globals).
__device__ float g_partial[CHUNKS][BATCH][NPTS];  // 4 MB
__device__ float g_min[BATCH];
__device__ int   g_cnt_b[BATCH];                  // per-batch arrival counters
__device__ int   g_cnt_all;                       // batch-completion counter

typedef unsigned long long u64;

// ---- packed f32x2 helpers ---------------------------------------------------
__device__ __forceinline__ void upk2(u64 v, float& a, float& b) {
    asm("mov.b64 {%0, %1}, %2;" : "=f"(a), "=f"(b) : "l"(v));
}
__device__ __forceinline__ u64 pk2(float a, float b) {
    u64 r; asm("mov.b64 %0, {%1, %2};" : "=l"(r) : "f"(a), "f"(b)); return r;
}
__device__ __forceinline__ u64 addx2(u64 a, u64 b) {
    u64 r; asm("add.rn.f32x2 %0, %1, %2;" : "=l"(r) : "l"(a), "l"(b)); return r;
}
__device__ __forceinline__ u64 mulx2(u64 a, u64 b) {
    u64 r; asm("mul.rn.f32x2 %0, %1, %2;" : "=l"(r) : "l"(a), "l"(b)); return r;
}
__device__ __forceinline__ u64 fmx2(u64 a, u64 b, u64 c) {
    u64 r; asm("fma.rn.f32x2 %0, %1, %2, %3;" : "=l"(r) : "l"(a), "l"(b), "l"(c)); return r;
}
__device__ __forceinline__ float sqrtapx(float x) {
    float r; asm("sqrt.approx.f32 %0, %1;" : "=f"(r) : "f"(x)); return r;
}

// Swizzle on u64 index, verified 2-way-optimal for the lane pattern m = C - 2t:
// residue n mod 16 = (m mod 16) + ((m>>4)&3) is hit by exactly 2 lanes.
__device__ __forceinline__ int swz(int m) { return m + ((m >> 4) & 3); }

// ---------------------------------------------------------------------------
// Single fused kernel.
// Grid (CHUNKS, BATCH), TPB=256. Thread t owns shifts 4t..4t+3, walks the
// chunk's j values in pairs. Negated target in 4 SoA u64-pair arrays
// (even-aligned and odd-aligned, x and y), swizzled; every shift alignment of
// a (j,j+1) pair is a direct LDS.64. m=2,3 reuse m=0,1's previous-iteration
// loads (register window). Zero pack MOVs; one swizzle + one IMAD per q.
// The last block per batch (atomic counter) reduces that batch; the last
// batch-reducer computes the final mean. All reductions fixed-order.
// ---------------------------------------------------------------------------
__global__ void __launch_bounds__(TPB, 5)
snake_kernel(const float2* __restrict__ x, const float2* __restrict__ tg,
             float* __restrict__ out)
{
    __shared__ __align__(16) u64 SH[4][PADN];   // 0:TXe 1:TXo 2:TYe 3:TYo (33 KB)
    __shared__ u64 XPX[NJP], XPY[NJP];
    __shared__ float redmin[8];
    __shared__ int lastflag;

    const int b     = blockIdx.y;
    const int chunk = blockIdx.x;
    const int j0    = chunk * JCH;
    const int t     = threadIdx.x;

    const float2* __restrict__ tb = tg + b * NPTS;
    const float2* __restrict__ xb = x  + b * NPTS;

    float* TXe = (float*)SH[0];
    float* TXo = (float*)SH[1];
    float* TYe = (float*)SH[2];
    float* TYo = (float*)SH[3];

    // Fill: TXe pair m = (-T[2m], -T[2m+1]); TXo pair m = (-T[2m+1], -T[2m+2])
    // over the duplicated 2N domain (indices mod N), swizzled.
    #pragma unroll
    for (int i = t; i < 2 * NPTS; i += TPB) {
        float2 tv = tb[i & (NPTS - 1)];
        float nx = -tv.x, ny = -tv.y;
        int pe = 2 * swz(i >> 1) + (i & 1);
        TXe[pe] = nx;  TYe[pe] = ny;
        int j  = (i + 2 * NPTS - 1) & (2 * NPTS - 1);   // i-1 mod 2N
        int po = 2 * swz(j >> 1) + (j & 1);
        TXo[po] = nx;  TYo[po] = ny;
    }
    if (t < NJP) {
        float4 q = *(const float4*)(xb + j0 + 2 * t);   // (xj.x,xj.y,xj1.x,xj1.y)
        XPX[t] = pk2(q.x, q.z);
        XPY[t] = pk2(q.y, q.w);
    }
    __syncthreads();

    const int s0 = 4 * t;                       // first shift owned
    const int P  = ((j0 + NPTS) >> 1) - 2 * t;  // even-pair u64 index at q=0 (>=2)

    float a0=0, a0h=0, a1=0, a1h=0, a2=0, a2h=0, a3=0, a3h=0;

    // Preload window: even pair P-1 (for m=2), odd pair P-2 (for m=3).
    int ie = swz(P - 1);
    int io = swz(P - 2);
    u64 axe = SH[0][ie], aye = SH[2][ie];
    u64 axo = SH[1][io], ayo = SH[3][io];
    int fo = ie;                                // phi(P+q-1) for q=0

    #pragma unroll 4
    for (int q = 0; q < NJP; ++q) {
        const int fe = swz(P + q);              // ONE fresh swizzle per q
        u64 bxe = SH[0][fe], bye = SH[2][fe];   // (T[e],T[e+1])      -> shift s0
        u64 bxo = SH[1][fo], byo = SH[3][fo];   // (T[e-1],T[e])      -> shift s0+1
        u64 xpx = XPX[q], xpy = XPY[q];         // broadcast

        {   // m=0
            u64 dx = addx2(xpx, bxe), dy = addx2(xpy, bye);
            u64 d2 = fmx2(dy, dy, mulx2(dx, dx));
            float lo, hi; upk2(d2, lo, hi);
            a0 += sqrtapx(lo); a0h += sqrtapx(hi);
        }
        {   // m=1
            u64 dx = addx2(xpx, bxo), dy = addx2(xpy, byo);
            u64 d2 = fmx2(dy, dy, mulx2(dx, dx));
            float lo, hi; upk2(d2, lo, hi);
            a1 += sqrtapx(lo); a1h += sqrtapx(hi);
        }
        {   // m=2: previous even pair (T[e-2],T[e-1])
            u64 dx = addx2(xpx, axe), dy = addx2(xpy, aye);
            u64 d2 = fmx2(dy, dy, mulx2(dx, dx));
            float lo, hi; upk2(d2, lo, hi);
            a2 += sqrtapx(lo); a2h += sqrtapx(hi);
        }
        {   // m=3: previous odd pair (T[e-3],T[e-2])
            u64 dx = addx2(xpx, axo), dy = addx2(xpy, ayo);
            u64 d2 = fmx2(dy, dy, mulx2(dx, dx));
            float lo, hi; upk2(d2, lo, hi);
            a3 += sqrtapx(lo); a3h += sqrtapx(hi);
        }

        axe = bxe; aye = bye; axo = bxo; ayo = byo;   // renamed under unroll
        fo = fe;
    }

    float4 outv = make_float4(a0 + a0h, a1 + a1h, a2 + a2h, a3 + a3h);
    *(float4*)&g_partial[chunk][b][s0] = outv;        // 16B aligned

    // ---- last block of this batch reduces it --------------------------------
    __threadfence();
    if (t == 0) {
        int old = atomicAdd(&g_cnt_b[b], 1);
        lastflag = (old == CHUNKS - 1);
    }
    __syncthreads();
    if (!lastflag) return;
    if (t == 0) g_cnt_b[b] = 0;                        // reset for next replay

    float mn = 3.4e38f;
    #pragma unroll
    for (int k = 0; k < 4; ++k) {
        int s = t + k * 256;
        float sum = 0.0f;
        #pragma unroll
        for (int c = 0; c < CHUNKS; ++c)
            sum += __ldcg(&g_partial[c][b][s]);
        mn = fminf(mn, sum);
    }
    #pragma unroll
    for (int o = 16; o > 0; o >>= 1)
        mn = fminf(mn, __shfl_xor_sync(0xFFFFFFFFu, mn, o));
    if ((t & 31) == 0) redmin[t >> 5] = mn;
    __syncthreads();

    if (t == 0) {
        float v = redmin[0];
        #pragma unroll
        for (int w = 1; w < 8; ++w) v = fminf(v, redmin[w]);
        g_min[b] = v;
        __threadfence();
        int old = atomicAdd(&g_cnt_all, 1);
        if (old == BATCH - 1) {                        // last batch-reducer
            g_cnt_all = 0;                             // reset for next replay
            float s = 0.0f;
            #pragma unroll
            for (int bb = 0; bb < BATCH; ++bb)
                s += __ldcg(&g_min[bb]);
            out[0] = s * (1.0f / (float)(BATCH * NPTS));
        }
    }
}

// ---------------------------------------------------------------------------
extern "C" void kernel_launch(void* const* d_in, const int* in_sizes, int n_in,
                              void* d_out, int out_size)
{
    const float2* x  = (const float2*)d_in[0];
    const float2* tg = (const float2*)d_in[1];
    float* out = (float*)d_out;

    dim3 grid(CHUNKS, BATCH);
    snake_kernel<<<grid, TPB>>>(x, tg, out);
}